// round 11
// baseline (speedup 1.0000x reference)
#include <cuda_runtime.h>
#include <cuda_fp16.h>
#include <cstdint>

#define OUTF 11008
#define INF  4096
#define ROWS 64
#define KCTA 256
#define WSTRIDE 132                    // 128 words + 4 pad: banks (4*gid+tg) bijective
#define GRID_X (OUTF / ROWS)           // 172
#define GRID_Y (INF / KCTA)            // 16

// x pre-split to fp16 hi/lo, layout [k2][batch] as half2-in-unsigned.
__device__ __align__(16) unsigned g_XH[(INF / 2) * 8];
__device__ __align__(16) unsigned g_XL[(INF / 2) * 8];

// Fused: zero the output AND split x into fp16 hi/lo slabs.
__global__ void prep_zero(const float* __restrict__ x, float4* __restrict__ out4, int nout4) {
    int i = blockIdx.x * blockDim.x + threadIdx.x;
    if (i < (INF / 2) * 8) {
        int k2 = i >> 3, n = i & 7;
        float f0 = x[n * INF + 2 * k2];
        float f1 = x[n * INF + 2 * k2 + 1];
        __half h0 = __float2half_rn(f0), h1 = __float2half_rn(f1);
        __half l0 = __float2half_rn(f0 - __half2float(h0));
        __half l1 = __float2half_rn(f1 - __half2float(h1));
        __half2 H = __halves2half2(h0, h1), L = __halves2half2(l0, l1);
        g_XH[i] = *reinterpret_cast<unsigned*>(&H);
        g_XL[i] = *reinterpret_cast<unsigned*>(&L);
    }
    if (i < nout4) out4[i] = make_float4(0.f, 0.f, 0.f, 0.f);
}

// Dequant one packed byte -> half2 (n_lo-8, n_hi-8), exact (Sterbenz).
__device__ __forceinline__ unsigned dq(unsigned v) {
    unsigned t = ((v | (v << 12)) & 0x000F000Fu) | 0x64006400u;  // fp16 (1024+n)
    unsigned c = 0xE408E408u;                                    // half2(-1032)
    __half2 h = __hadd2(*reinterpret_cast<__half2*>(&t),
                        *reinterpret_cast<__half2*>(&c));
    return *reinterpret_cast<unsigned*>(&h);
}

__device__ __forceinline__ void mma16816(float& d0, float& d1, float& d2, float& d3,
                                         unsigned a0, unsigned a1, unsigned a2, unsigned a3,
                                         unsigned b0, unsigned b1) {
    asm volatile(
        "mma.sync.aligned.m16n8k16.row.col.f32.f16.f16.f32 "
        "{%0,%1,%2,%3},{%4,%5,%6,%7},{%8,%9},{%0,%1,%2,%3};"
        : "+f"(d0), "+f"(d1), "+f"(d2), "+f"(d3)
        : "r"(a0), "r"(a1), "r"(a2), "r"(a3), "r"(b0), "r"(b1));
}

__device__ __forceinline__ void cpa16(void* smem, const void* gmem) {
    unsigned s = (unsigned)__cvta_generic_to_shared(smem);
    asm volatile("cp.async.cg.shared.global [%0], [%1], 16;" :: "r"(s), "l"(gmem));
}

__global__ __launch_bounds__(128, 5)
void qlin_kernel(const int*   __restrict__ packed,
                 const float* __restrict__ scales,
                 float*       __restrict__ out) {
    __shared__ __align__(16) unsigned Wsm[ROWS * WSTRIDE];      // 33792 B
    __shared__ __align__(16) unsigned xhs[(KCTA / 2) * 8];      // 4096 B
    __shared__ __align__(16) unsigned xls[(KCTA / 2) * 8];      // 4096 B
    __shared__ __align__(16) float    ssm[ROWS * 9];            // 2304 B

    const int tid  = threadIdx.x;
    const int lane = tid & 31, warp = tid >> 5;
    const int gid  = lane >> 2, tg = lane & 3;
    const int rowbase = blockIdx.x * ROWS;
    const int kbase   = blockIdx.y * KCTA;
    const int kb2     = kbase >> 1;

    const int* pg = packed + (size_t)rowbase * (INF / 2) + kb2;

    // ── Group A: x slabs + W first half (words 0..63 of each row).
    {
        const int4* gh = reinterpret_cast<const int4*>(g_XH + kb2 * 8);
        const int4* gl = reinterpret_cast<const int4*>(g_XL + kb2 * 8);
        cpa16(reinterpret_cast<int4*>(xhs) + tid,       gh + tid);
        cpa16(reinterpret_cast<int4*>(xhs) + 128 + tid, gh + 128 + tid);
        cpa16(reinterpret_cast<int4*>(xls) + tid,       gl + tid);
        cpa16(reinterpret_cast<int4*>(xls) + 128 + tid, gl + 128 + tid);
        // W first half: 64 rows x 16 int4 = 1024 int4; 8 per thread.
        #pragma unroll
        for (int p = 0; p < 8; p++) {
            int idx = p * 128 + tid;
            int row = idx >> 4, q = idx & 15;
            cpa16(&Wsm[row * WSTRIDE + q * 4], pg + (size_t)row * (INF / 2) + q * 4);
        }
    }
    asm volatile("cp.async.commit_group;" ::: "memory");
    // ── Group B: W second half (words 64..127).
    {
        #pragma unroll
        for (int p = 0; p < 8; p++) {
            int idx = p * 128 + tid;
            int row = idx >> 4, q = idx & 15;
            cpa16(&Wsm[row * WSTRIDE + 64 + q * 4],
                  pg + (size_t)row * (INF / 2) + 64 + q * 4);
        }
    }
    asm volatile("cp.async.commit_group;" ::: "memory");

    // ── Scales: plain LDG.128 + scalar STS (smem stride 9 is not 16B-aligned,
    // so cp.async is illegal here — this was the R10 fault).
    if (tid < ROWS) {
        const float* sg = scales + (size_t)(rowbase + tid) * (INF / 32) + (kbase >> 5);
        float4 a = *reinterpret_cast<const float4*>(sg);
        float4 b = *reinterpret_cast<const float4*>(sg + 4);
        float* d = &ssm[tid * 9];
        d[0] = a.x; d[1] = a.y; d[2] = a.z; d[3] = a.w;
        d[4] = b.x; d[5] = b.y; d[6] = b.z; d[7] = b.w;
    }

    const int r0 = warp * 16 + gid;                 // rows r0 and r0+8
    const unsigned* wr0 = &Wsm[r0 * WSTRIDE];
    const unsigned* wr8 = wr0 + 8 * WSTRIDE;

    float acc0 = 0.f, acc1 = 0.f, acc2 = 0.f, acc3 = 0.f;

    #pragma unroll
    for (int half = 0; half < 2; half++) {
        if (half == 0)
            asm volatile("cp.async.wait_group 1;" ::: "memory");
        else
            asm volatile("cp.async.wait_group 0;" ::: "memory");
        __syncthreads();

        #pragma unroll
        for (int bb = 0; bb < 4; bb++) {            // q4 block = 32 cols = 2 k-tiles
            const int blk = half * 4 + bb;
            float t0 = 0.f, t1 = 0.f, t2 = 0.f, t3 = 0.f;
            #pragma unroll
            for (int u = 0; u < 2; u++) {
                const int t = blk * 2 + u;
                const int j = 8 * t + tg;           // word j -> cols (2j, 2j+1)
                unsigned a0 = dq(wr0[j]);
                unsigned a1 = dq(wr8[j]);
                unsigned a2 = dq(wr0[j + 4]);
                unsigned a3 = dq(wr8[j + 4]);
                unsigned bh0 = xhs[j * 8 + gid];
                unsigned bh1 = xhs[(j + 4) * 8 + gid];
                unsigned bl0 = xls[j * 8 + gid];
                unsigned bl1 = xls[(j + 4) * 8 + gid];
                mma16816(t0, t1, t2, t3, a0, a1, a2, a3, bh0, bh1);
                mma16816(t0, t1, t2, t3, a0, a1, a2, a3, bl0, bl1);
            }
            float s0 = ssm[r0 * 9 + blk];
            float s8 = ssm[(r0 + 8) * 9 + blk];
            acc0 = fmaf(s0, t0, acc0);
            acc1 = fmaf(s0, t1, acc1);
            acc2 = fmaf(s8, t2, acc2);
            acc3 = fmaf(s8, t3, acc3);
        }
    }

    // ── Epilogue: D frag -> out[batch][row]; 4 atomics/lane, no reduction.
    const int gr0 = rowbase + r0, gr8 = gr0 + 8;
    atomicAdd(&out[(size_t)(2 * tg)     * OUTF + gr0], acc0);
    atomicAdd(&out[(size_t)(2 * tg + 1) * OUTF + gr0], acc1);
    atomicAdd(&out[(size_t)(2 * tg)     * OUTF + gr8], acc2);
    atomicAdd(&out[(size_t)(2 * tg + 1) * OUTF + gr8], acc3);
}

extern "C" void kernel_launch(void* const* d_in, const int* in_sizes, int n_in,
                              void* d_out, int out_size) {
    const float* x      = (const float*)d_in[0];
    const int*   packed = (const int*)d_in[1];
    const float* scales = (const float*)d_in[2];
    float*       out    = (float*)d_out;

    int nout4 = out_size / 4;
    int naux  = (INF / 2) * 8;
    int nthr  = nout4 > naux ? nout4 : naux;
    prep_zero<<<(nthr + 255) / 256, 256>>>(x, (float4*)out, nout4);

    dim3 grid(GRID_X, GRID_Y);                      // (172, 16) = 2752 CTAs
    qlin_kernel<<<grid, 128>>>(packed, scales, out);
}

// round 12
// speedup vs baseline: 1.0490x; 1.0490x over previous
#include <cuda_runtime.h>
#include <cuda_fp16.h>
#include <cstdint>

#define OUTF 11008
#define INF  4096
#define ROWS 64
#define KCTA 256
#define WSTRIDE 132                    // 128 words + 4 pad: banks (4*gid+tg) bijective
#define GRID_X (OUTF / ROWS)           // 172
#define GRID_Y (INF / KCTA)            // 16

// x pre-split to fp16 hi/lo, layout [k2][batch] as half2-in-unsigned.
__device__ __align__(16) unsigned g_XH[(INF / 2) * 8];
__device__ __align__(16) unsigned g_XL[(INF / 2) * 8];

// Fused: zero the output AND split x into fp16 hi/lo slabs.
__global__ void prep_zero(const float* __restrict__ x, float4* __restrict__ out4, int nout4) {
    int i = blockIdx.x * blockDim.x + threadIdx.x;
    if (i < (INF / 2) * 8) {
        int k2 = i >> 3, n = i & 7;
        float f0 = x[n * INF + 2 * k2];
        float f1 = x[n * INF + 2 * k2 + 1];
        __half h0 = __float2half_rn(f0), h1 = __float2half_rn(f1);
        __half l0 = __float2half_rn(f0 - __half2float(h0));
        __half l1 = __float2half_rn(f1 - __half2float(h1));
        __half2 H = __halves2half2(h0, h1), L = __halves2half2(l0, l1);
        g_XH[i] = *reinterpret_cast<unsigned*>(&H);
        g_XL[i] = *reinterpret_cast<unsigned*>(&L);
    }
    if (i < nout4) out4[i] = make_float4(0.f, 0.f, 0.f, 0.f);
}

// Dequant one packed byte -> half2 (n_lo-8, n_hi-8), exact (Sterbenz).
__device__ __forceinline__ unsigned dq(unsigned v) {
    unsigned t = ((v | (v << 12)) & 0x000F000Fu) | 0x64006400u;  // fp16 (1024+n)
    unsigned c = 0xE408E408u;                                    // half2(-1032)
    __half2 h = __hadd2(*reinterpret_cast<__half2*>(&t),
                        *reinterpret_cast<__half2*>(&c));
    return *reinterpret_cast<unsigned*>(&h);
}

__device__ __forceinline__ void mma16816(float& d0, float& d1, float& d2, float& d3,
                                         unsigned a0, unsigned a1, unsigned a2, unsigned a3,
                                         unsigned b0, unsigned b1) {
    asm volatile(
        "mma.sync.aligned.m16n8k16.row.col.f32.f16.f16.f32 "
        "{%0,%1,%2,%3},{%4,%5,%6,%7},{%8,%9},{%0,%1,%2,%3};"
        : "+f"(d0), "+f"(d1), "+f"(d2), "+f"(d3)
        : "r"(a0), "r"(a1), "r"(a2), "r"(a3), "r"(b0), "r"(b1));
}

// cp.async with L2 evict_last hint: keeps W resident in L2 across graph replays.
__device__ __forceinline__ void cpa16_el(void* smem, const void* gmem, uint64_t pol) {
    unsigned s = (unsigned)__cvta_generic_to_shared(smem);
    asm volatile("cp.async.cg.shared.global.L2::cache_hint [%0], [%1], 16, %2;"
                 :: "r"(s), "l"(gmem), "l"(pol));
}
__device__ __forceinline__ void cpa16(void* smem, const void* gmem) {
    unsigned s = (unsigned)__cvta_generic_to_shared(smem);
    asm volatile("cp.async.cg.shared.global [%0], [%1], 16;" :: "r"(s), "l"(gmem));
}

__global__ __launch_bounds__(128, 5)
void qlin_kernel(const int*   __restrict__ packed,
                 const float* __restrict__ scales,
                 float*       __restrict__ out) {
    __shared__ __align__(16) unsigned Wsm[ROWS * WSTRIDE];      // 33792 B
    __shared__ __align__(16) unsigned xhs[(KCTA / 2) * 8];      // 4096 B
    __shared__ __align__(16) unsigned xls[(KCTA / 2) * 8];      // 4096 B
    __shared__ __align__(16) float    ssm[ROWS * 9];            // 2304 B

    const int tid  = threadIdx.x;
    const int lane = tid & 31, warp = tid >> 5;
    const int gid  = lane >> 2, tg = lane & 3;
    const int rowbase = blockIdx.x * ROWS;
    const int kbase   = blockIdx.y * KCTA;
    const int kb2     = kbase >> 1;

    const int* pg = packed + (size_t)rowbase * (INF / 2) + kb2;

    uint64_t pol;
    asm("createpolicy.fractional.L2::evict_last.b64 %0, 1.0;" : "=l"(pol));

    // ── Group A: x slabs + W first half (words 0..63 of each row).
    {
        const int4* gh = reinterpret_cast<const int4*>(g_XH + kb2 * 8);
        const int4* gl = reinterpret_cast<const int4*>(g_XL + kb2 * 8);
        cpa16(reinterpret_cast<int4*>(xhs) + tid,       gh + tid);
        cpa16(reinterpret_cast<int4*>(xhs) + 128 + tid, gh + 128 + tid);
        cpa16(reinterpret_cast<int4*>(xls) + tid,       gl + tid);
        cpa16(reinterpret_cast<int4*>(xls) + 128 + tid, gl + 128 + tid);
        #pragma unroll
        for (int p = 0; p < 8; p++) {
            int idx = p * 128 + tid;
            int row = idx >> 4, q = idx & 15;
            cpa16_el(&Wsm[row * WSTRIDE + q * 4], pg + (size_t)row * (INF / 2) + q * 4, pol);
        }
    }
    asm volatile("cp.async.commit_group;" ::: "memory");
    // ── Group B: W second half (words 64..127).
    {
        #pragma unroll
        for (int p = 0; p < 8; p++) {
            int idx = p * 128 + tid;
            int row = idx >> 4, q = idx & 15;
            cpa16_el(&Wsm[row * WSTRIDE + 64 + q * 4],
                     pg + (size_t)row * (INF / 2) + 64 + q * 4, pol);
        }
    }
    asm volatile("cp.async.commit_group;" ::: "memory");

    // ── Scales: plain LDG.128 (evict_last hint) + scalar STS.
    if (tid < ROWS) {
        const float* sg = scales + (size_t)(rowbase + tid) * (INF / 32) + (kbase >> 5);
        float4 a, b;
        asm("ld.global.nc.L2::cache_hint.v4.f32 {%0,%1,%2,%3}, [%4], %5;"
            : "=f"(a.x), "=f"(a.y), "=f"(a.z), "=f"(a.w) : "l"(sg), "l"(pol));
        asm("ld.global.nc.L2::cache_hint.v4.f32 {%0,%1,%2,%3}, [%4], %5;"
            : "=f"(b.x), "=f"(b.y), "=f"(b.z), "=f"(b.w) : "l"(sg + 4), "l"(pol));
        float* d = &ssm[tid * 9];
        d[0] = a.x; d[1] = a.y; d[2] = a.z; d[3] = a.w;
        d[4] = b.x; d[5] = b.y; d[6] = b.z; d[7] = b.w;
    }

    const int r0 = warp * 16 + gid;                 // rows r0 and r0+8
    const unsigned* wr0 = &Wsm[r0 * WSTRIDE];
    const unsigned* wr8 = wr0 + 8 * WSTRIDE;

    float acc0 = 0.f, acc1 = 0.f, acc2 = 0.f, acc3 = 0.f;

    #pragma unroll
    for (int half = 0; half < 2; half++) {
        if (half == 0)
            asm volatile("cp.async.wait_group 1;" ::: "memory");
        else
            asm volatile("cp.async.wait_group 0;" ::: "memory");
        __syncthreads();

        #pragma unroll
        for (int bb = 0; bb < 4; bb++) {            // q4 block = 32 cols = 2 k-tiles
            const int blk = half * 4 + bb;
            float t0 = 0.f, t1 = 0.f, t2 = 0.f, t3 = 0.f;
            #pragma unroll
            for (int u = 0; u < 2; u++) {
                const int t = blk * 2 + u;
                const int j = 8 * t + tg;           // word j -> cols (2j, 2j+1)
                unsigned a0 = dq(wr0[j]);
                unsigned a1 = dq(wr8[j]);
                unsigned a2 = dq(wr0[j + 4]);
                unsigned a3 = dq(wr8[j + 4]);
                unsigned bh0 = xhs[j * 8 + gid];
                unsigned bh1 = xhs[(j + 4) * 8 + gid];
                unsigned bl0 = xls[j * 8 + gid];
                unsigned bl1 = xls[(j + 4) * 8 + gid];
                mma16816(t0, t1, t2, t3, a0, a1, a2, a3, bh0, bh1);
                mma16816(t0, t1, t2, t3, a0, a1, a2, a3, bl0, bl1);
            }
            float s0 = ssm[r0 * 9 + blk];
            float s8 = ssm[(r0 + 8) * 9 + blk];
            acc0 = fmaf(s0, t0, acc0);
            acc1 = fmaf(s0, t1, acc1);
            acc2 = fmaf(s8, t2, acc2);
            acc3 = fmaf(s8, t3, acc3);
        }
    }

    // ── Epilogue: D frag -> out[batch][row]; 4 atomics/lane, no reduction.
    const int gr0 = rowbase + r0, gr8 = gr0 + 8;
    atomicAdd(&out[(size_t)(2 * tg)     * OUTF + gr0], acc0);
    atomicAdd(&out[(size_t)(2 * tg + 1) * OUTF + gr0], acc1);
    atomicAdd(&out[(size_t)(2 * tg)     * OUTF + gr8], acc2);
    atomicAdd(&out[(size_t)(2 * tg + 1) * OUTF + gr8], acc3);
}

extern "C" void kernel_launch(void* const* d_in, const int* in_sizes, int n_in,
                              void* d_out, int out_size) {
    const float* x      = (const float*)d_in[0];
    const int*   packed = (const int*)d_in[1];
    const float* scales = (const float*)d_in[2];
    float*       out    = (float*)d_out;

    int nout4 = out_size / 4;
    int naux  = (INF / 2) * 8;
    int nthr  = nout4 > naux ? nout4 : naux;
    prep_zero<<<(nthr + 255) / 256, 256>>>(x, (float4*)out, nout4);

    dim3 grid(GRID_X, GRID_Y);                      // (172, 16) = 2752 CTAs
    qlin_kernel<<<grid, 128>>>(packed, scales, out);
}